// round 1
// baseline (speedup 1.0000x reference)
#include <cuda_runtime.h>

#define N_NODES 150000
#define N_EDGES 2400000
#define D 128
#define ROWS_PER_BLK 64
#define A_STRIDE 132   // 128 + 4 pad: kills 8-way bank conflicts on column reads

// 76.8 MB scratch for the SpMM result (allowed: __device__ global, no runtime alloc)
__device__ float g_side[(size_t)N_NODES * D];

// Shared layout (floats): Wgc[128*128] | Wbi[128*128] | S[64*132] | B[64*132]
#define SMEM_FLOATS (2 * 128 * 128 + 2 * ROWS_PER_BLK * A_STRIDE)
#define SMEM_BYTES (SMEM_FLOATS * 4)

__global__ void zero_side_kernel() {
    size_t i = (size_t)blockIdx.x * blockDim.x + threadIdx.x;
    size_t n4 = (size_t)N_NODES * D / 4;
    if (i < n4) reinterpret_cast<float4*>(g_side)[i] = make_float4(0.f, 0.f, 0.f, 0.f);
}

// One warp per edge: lane l handles floats [4l, 4l+4) of the row.
__global__ void spmm_kernel(const int* __restrict__ erow,
                            const int* __restrict__ ecol,
                            const float* __restrict__ eval,
                            const float* __restrict__ ego) {
    int gid = blockIdx.x * blockDim.x + threadIdx.x;
    int e = gid >> 5;
    int lane = gid & 31;
    if (e >= N_EDGES) return;
    int r = erow[e];
    int c = ecol[e];
    float v = eval[e];
    float4 m = reinterpret_cast<const float4*>(ego + (size_t)c * D)[lane];
    m.x *= v; m.y *= v; m.z *= v; m.w *= v;
    float* dst = g_side + (size_t)r * D + lane * 4;
    asm volatile("red.global.add.v4.f32 [%0], {%1,%2,%3,%4};"
                 :: "l"(dst), "f"(m.x), "f"(m.y), "f"(m.z), "f"(m.w)
                 : "memory");
}

// Fused: sum_emb = leaky(side @ Wgc + bgc); bi_emb = leaky((ego*side) @ Wbi + bbi);
// out = l2_normalize(sum_emb + bi_emb, axis=1)
// Block: 256 threads = 16 col-threads x 16 row-threads; thread tile = 4 rows x 8 cols.
__global__ __launch_bounds__(256, 1)
void dense_kernel(const float* __restrict__ ego,
                  const float* __restrict__ wgc, const float* __restrict__ bgc,
                  const float* __restrict__ wbi, const float* __restrict__ bbi,
                  float* __restrict__ out) {
    extern __shared__ float sh[];
    float* sWgc = sh;                       // [128][128]
    float* sWbi = sWgc + 128 * 128;         // [128][128]
    float* sS   = sWbi + 128 * 128;         // [64][132]
    float* sB   = sS + ROWS_PER_BLK * A_STRIDE; // [64][132]

    const int tid = threadIdx.x;
    const long row0 = (long)blockIdx.x * ROWS_PER_BLK;

    // Load both weight matrices (4096 float4 each), coalesced.
    for (int i = tid; i < 4096; i += 256) {
        reinterpret_cast<float4*>(sWgc)[i] = reinterpret_cast<const float4*>(wgc)[i];
        reinterpret_cast<float4*>(sWbi)[i] = reinterpret_cast<const float4*>(wbi)[i];
    }
    // Load 64-row tiles of side and ego*side. 2048 float4 per tile.
    for (int i = tid; i < ROWS_PER_BLK * 32; i += 256) {
        int r = i >> 5;
        int c4 = i & 31;
        long gr = row0 + r;
        float4 s4 = make_float4(0.f, 0.f, 0.f, 0.f);
        float4 b4 = s4;
        if (gr < N_NODES) {
            s4 = reinterpret_cast<const float4*>(g_side + gr * D)[c4];
            float4 e4 = reinterpret_cast<const float4*>(ego + gr * D)[c4];
            b4 = make_float4(s4.x * e4.x, s4.y * e4.y, s4.z * e4.z, s4.w * e4.w);
        }
        reinterpret_cast<float4*>(sS + r * A_STRIDE)[c4] = s4;
        reinterpret_cast<float4*>(sB + r * A_STRIDE)[c4] = b4;
    }
    __syncthreads();

    const int col_t = tid & 15;   // 16 col-threads -> 8 cols each
    const int row_t = tid >> 4;   // 16 row-threads -> 4 rows each
    const int c0 = col_t * 8;
    const int r0 = row_t * 4;

    float acc1[4][8];
    float acc2[4][8];
#pragma unroll
    for (int i = 0; i < 4; i++)
#pragma unroll
        for (int j = 0; j < 8; j++) { acc1[i][j] = 0.f; acc2[i][j] = 0.f; }

#pragma unroll 4
    for (int k = 0; k < 128; k++) {
        float wg[8], wb[8];
        *reinterpret_cast<float4*>(wg)     = *reinterpret_cast<const float4*>(sWgc + k * 128 + c0);
        *reinterpret_cast<float4*>(wg + 4) = *reinterpret_cast<const float4*>(sWgc + k * 128 + c0 + 4);
        *reinterpret_cast<float4*>(wb)     = *reinterpret_cast<const float4*>(sWbi + k * 128 + c0);
        *reinterpret_cast<float4*>(wb + 4) = *reinterpret_cast<const float4*>(sWbi + k * 128 + c0 + 4);
        float sv[4], bv[4];
#pragma unroll
        for (int i = 0; i < 4; i++) {
            sv[i] = sS[(r0 + i) * A_STRIDE + k];
            bv[i] = sB[(r0 + i) * A_STRIDE + k];
        }
#pragma unroll
        for (int i = 0; i < 4; i++)
#pragma unroll
            for (int j = 0; j < 8; j++) {
                acc1[i][j] = fmaf(sv[i], wg[j], acc1[i][j]);
                acc2[i][j] = fmaf(bv[i], wb[j], acc2[i][j]);
            }
    }

    // Bias, leaky_relu, sum, row L2-normalize, store.
    float bg[8], bb[8];
    *reinterpret_cast<float4*>(bg)     = *reinterpret_cast<const float4*>(bgc + c0);
    *reinterpret_cast<float4*>(bg + 4) = *reinterpret_cast<const float4*>(bgc + c0 + 4);
    *reinterpret_cast<float4*>(bb)     = *reinterpret_cast<const float4*>(bbi + c0);
    *reinterpret_cast<float4*>(bb + 4) = *reinterpret_cast<const float4*>(bbi + c0 + 4);

#pragma unroll
    for (int i = 0; i < 4; i++) {
        float sq = 0.f;
#pragma unroll
        for (int j = 0; j < 8; j++) {
            float x1 = acc1[i][j] + bg[j];
            x1 = fmaxf(x1, 0.2f * x1);          // leaky_relu, slope 0.2
            float x2 = acc2[i][j] + bb[j];
            x2 = fmaxf(x2, 0.2f * x2);
            float v = x1 + x2;
            acc1[i][j] = v;                      // reuse as e
            sq = fmaf(v, v, sq);
        }
        // reduce across the 16 col-threads (lanes {0..15} or {16..31})
#pragma unroll
        for (int m = 8; m >= 1; m >>= 1)
            sq += __shfl_xor_sync(0xffffffffu, sq, m);
        long gr = row0 + r0 + i;
        if (gr < N_NODES) {
            float rn = rsqrtf(fmaxf(sq, 1e-12f));
            float4 o0 = make_float4(acc1[i][0] * rn, acc1[i][1] * rn,
                                    acc1[i][2] * rn, acc1[i][3] * rn);
            float4 o1 = make_float4(acc1[i][4] * rn, acc1[i][5] * rn,
                                    acc1[i][6] * rn, acc1[i][7] * rn);
            reinterpret_cast<float4*>(out + gr * D + c0)[0] = o0;
            reinterpret_cast<float4*>(out + gr * D + c0)[1] = o1;
        }
    }
}

extern "C" void kernel_launch(void* const* d_in, const int* in_sizes, int n_in,
                              void* d_out, int out_size) {
    const int*   erow = (const int*)d_in[0];
    const int*   ecol = (const int*)d_in[1];
    const float* eval = (const float*)d_in[2];
    const float* ego  = (const float*)d_in[3];
    const float* wgc  = (const float*)d_in[4];
    const float* bgc  = (const float*)d_in[5];
    const float* wbi  = (const float*)d_in[6];
    const float* bbi  = (const float*)d_in[7];
    float* out = (float*)d_out;

    // 1) zero the scatter target
    size_t n4 = (size_t)N_NODES * D / 4;
    zero_side_kernel<<<(int)((n4 + 255) / 256), 256>>>();

    // 2) SpMM scatter: one warp per edge
    long total_threads = (long)N_EDGES * 32;
    spmm_kernel<<<(int)((total_threads + 255) / 256), 256>>>(erow, ecol, eval, ego);

    // 3) fused dense transform + leaky_relu + l2 normalize
    cudaFuncSetAttribute(dense_kernel, cudaFuncAttributeMaxDynamicSharedMemorySize, SMEM_BYTES);
    dense_kernel<<<(N_NODES + ROWS_PER_BLK - 1) / ROWS_PER_BLK, 256, SMEM_BYTES>>>(
        ego, wgc, bgc, wbi, bbi, out);
}

// round 4
// speedup vs baseline: 1.2966x; 1.2966x over previous
#include <cuda_runtime.h>
#include <cstdint>

#define N_NODES 150000
#define N_EDGES 2400000
#define D 128
#define ROWS_PER_BLK 64
#define A_STRIDE 132

#define SCAN_TILE 1024
#define SCAN_BLOCKS ((N_NODES + SCAN_TILE - 1) / SCAN_TILE)   // 147

// ------------------------- device scratch (no runtime alloc) -------------------------
__device__ float g_side[(size_t)N_NODES * D];     // 76.8 MB
__device__ int   g_cnt[N_NODES];                  // per-row edge counts
__device__ int   g_start[N_NODES];                // CSR row start (exclusive scan)
__device__ int   g_cursor[N_NODES];               // fill cursors
__device__ int   g_blocksums[SCAN_BLOCKS];
__device__ int   g_ecol_s[N_EDGES];               // CSR-ordered cols
__device__ float g_eval_s[N_EDGES];               // CSR-ordered vals

// ------------------------- CSR build -------------------------
__global__ void zero_cnt_kernel() {
    int i = blockIdx.x * blockDim.x + threadIdx.x;
    if (i < N_NODES) g_cnt[i] = 0;
}

__global__ void hist_kernel(const int* __restrict__ erow) {
    int e = blockIdx.x * blockDim.x + threadIdx.x;
    if (e < N_EDGES) atomicAdd(&g_cnt[erow[e]], 1);
}

// per-block exclusive scan over tiles of 1024 counts (256 threads x 4 items)
__global__ void scan1_kernel() {
    __shared__ int sh[256];
    int t = threadIdx.x;
    int base = blockIdx.x * SCAN_TILE + t * 4;
    int v[4];
#pragma unroll
    for (int j = 0; j < 4; j++)
        v[j] = (base + j < N_NODES) ? g_cnt[base + j] : 0;
    int s = v[0] + v[1] + v[2] + v[3];
    sh[t] = s;
    __syncthreads();
#pragma unroll
    for (int off = 1; off < 256; off <<= 1) {
        int x = (t >= off) ? sh[t - off] : 0;
        __syncthreads();
        sh[t] += x;
        __syncthreads();
    }
    int excl = sh[t] - s;   // exclusive offset of this thread within block
    int run = excl;
#pragma unroll
    for (int j = 0; j < 4; j++) {
        if (base + j < N_NODES) g_start[base + j] = run;
        run += v[j];
    }
    if (t == 255) g_blocksums[blockIdx.x] = sh[255];
}

// single-block exclusive scan over block sums
__global__ void scan2_kernel() {
    __shared__ int sh[256];
    int t = threadIdx.x;
    int v = (t < SCAN_BLOCKS) ? g_blocksums[t] : 0;
    sh[t] = v;
    __syncthreads();
#pragma unroll
    for (int off = 1; off < 256; off <<= 1) {
        int x = (t >= off) ? sh[t - off] : 0;
        __syncthreads();
        sh[t] += x;
        __syncthreads();
    }
    if (t < SCAN_BLOCKS) g_blocksums[t] = sh[t] - v;
}

// add block offsets; init cursors
__global__ void scan3_kernel() {
    int i = blockIdx.x * blockDim.x + threadIdx.x;
    if (i < N_NODES) {
        int s = g_start[i] + g_blocksums[i / SCAN_TILE];
        g_start[i] = s;
        g_cursor[i] = s;
    }
}

__global__ void fill_kernel(const int* __restrict__ erow,
                            const int* __restrict__ ecol,
                            const float* __restrict__ eval) {
    int e = blockIdx.x * blockDim.x + threadIdx.x;
    if (e < N_EDGES) {
        int r = erow[e];
        int pos = atomicAdd(&g_cursor[r], 1);
        g_ecol_s[pos] = ecol[e];
        g_eval_s[pos] = eval[e];
    }
}

// ------------------------- SpMM: warp per row, register accumulation -------------------------
__global__ __launch_bounds__(256)
void spmm_csr_kernel(const float* __restrict__ ego) {
    int gw = (blockIdx.x * blockDim.x + threadIdx.x) >> 5;
    int lane = threadIdx.x & 31;
    if (gw >= N_NODES) return;
    int start = g_start[gw];
    int end = start + g_cnt[gw];
    const float4* ego4 = (const float4*)ego;
    float4 acc = make_float4(0.f, 0.f, 0.f, 0.f);
    int i = start;
    for (; i + 1 < end; i += 2) {
        int c0 = g_ecol_s[i];
        int c1 = g_ecol_s[i + 1];
        float v0 = g_eval_s[i];
        float v1 = g_eval_s[i + 1];
        float4 m0 = ego4[(size_t)c0 * 32 + lane];
        float4 m1 = ego4[(size_t)c1 * 32 + lane];
        acc.x = fmaf(v0, m0.x, acc.x); acc.y = fmaf(v0, m0.y, acc.y);
        acc.z = fmaf(v0, m0.z, acc.z); acc.w = fmaf(v0, m0.w, acc.w);
        acc.x = fmaf(v1, m1.x, acc.x); acc.y = fmaf(v1, m1.y, acc.y);
        acc.z = fmaf(v1, m1.z, acc.z); acc.w = fmaf(v1, m1.w, acc.w);
    }
    if (i < end) {
        int c0 = g_ecol_s[i];
        float v0 = g_eval_s[i];
        float4 m0 = ego4[(size_t)c0 * 32 + lane];
        acc.x = fmaf(v0, m0.x, acc.x); acc.y = fmaf(v0, m0.y, acc.y);
        acc.z = fmaf(v0, m0.z, acc.z); acc.w = fmaf(v0, m0.w, acc.w);
    }
    reinterpret_cast<float4*>(g_side)[(size_t)gw * 32 + lane] = acc;
}

// ------------------------- fused dense transform (round-1, known good) -------------------------
#define SMEM_FLOATS (2 * 128 * 128 + 2 * ROWS_PER_BLK * A_STRIDE)
#define SMEM_BYTES (SMEM_FLOATS * 4)

__global__ __launch_bounds__(256, 1)
void dense_kernel(const float* __restrict__ ego,
                  const float* __restrict__ wgc, const float* __restrict__ bgc,
                  const float* __restrict__ wbi, const float* __restrict__ bbi,
                  float* __restrict__ out) {
    extern __shared__ float sh[];
    float* sWgc = sh;
    float* sWbi = sWgc + 128 * 128;
    float* sS   = sWbi + 128 * 128;
    float* sB   = sS + ROWS_PER_BLK * A_STRIDE;

    const int tid = threadIdx.x;
    const long row0 = (long)blockIdx.x * ROWS_PER_BLK;

    for (int i = tid; i < 4096; i += 256) {
        reinterpret_cast<float4*>(sWgc)[i] = reinterpret_cast<const float4*>(wgc)[i];
        reinterpret_cast<float4*>(sWbi)[i] = reinterpret_cast<const float4*>(wbi)[i];
    }
    for (int i = tid; i < ROWS_PER_BLK * 32; i += 256) {
        int r = i >> 5;
        int c4 = i & 31;
        long gr = row0 + r;
        float4 s4 = make_float4(0.f, 0.f, 0.f, 0.f);
        float4 b4 = s4;
        if (gr < N_NODES) {
            s4 = reinterpret_cast<const float4*>(g_side + gr * D)[c4];
            float4 e4 = reinterpret_cast<const float4*>(ego + gr * D)[c4];
            b4 = make_float4(s4.x * e4.x, s4.y * e4.y, s4.z * e4.z, s4.w * e4.w);
        }
        reinterpret_cast<float4*>(sS + r * A_STRIDE)[c4] = s4;
        reinterpret_cast<float4*>(sB + r * A_STRIDE)[c4] = b4;
    }
    __syncthreads();

    const int col_t = tid & 15;
    const int row_t = tid >> 4;
    const int c0 = col_t * 8;
    const int r0 = row_t * 4;

    float acc1[4][8];
    float acc2[4][8];
#pragma unroll
    for (int i = 0; i < 4; i++)
#pragma unroll
        for (int j = 0; j < 8; j++) { acc1[i][j] = 0.f; acc2[i][j] = 0.f; }

#pragma unroll 4
    for (int k = 0; k < 128; k++) {
        float wg[8], wb[8];
        *reinterpret_cast<float4*>(wg)     = *reinterpret_cast<const float4*>(sWgc + k * 128 + c0);
        *reinterpret_cast<float4*>(wg + 4) = *reinterpret_cast<const float4*>(sWgc + k * 128 + c0 + 4);
        *reinterpret_cast<float4*>(wb)     = *reinterpret_cast<const float4*>(sWbi + k * 128 + c0);
        *reinterpret_cast<float4*>(wb + 4) = *reinterpret_cast<const float4*>(sWbi + k * 128 + c0 + 4);
        float sv[4], bv[4];
#pragma unroll
        for (int i = 0; i < 4; i++) {
            sv[i] = sS[(r0 + i) * A_STRIDE + k];
            bv[i] = sB[(r0 + i) * A_STRIDE + k];
        }
#pragma unroll
        for (int i = 0; i < 4; i++)
#pragma unroll
            for (int j = 0; j < 8; j++) {
                acc1[i][j] = fmaf(sv[i], wg[j], acc1[i][j]);
                acc2[i][j] = fmaf(bv[i], wb[j], acc2[i][j]);
            }
    }

    float bg[8], bb[8];
    *reinterpret_cast<float4*>(bg)     = *reinterpret_cast<const float4*>(bgc + c0);
    *reinterpret_cast<float4*>(bg + 4) = *reinterpret_cast<const float4*>(bgc + c0 + 4);
    *reinterpret_cast<float4*>(bb)     = *reinterpret_cast<const float4*>(bbi + c0);
    *reinterpret_cast<float4*>(bb + 4) = *reinterpret_cast<const float4*>(bbi + c0 + 4);

#pragma unroll
    for (int i = 0; i < 4; i++) {
        float sq = 0.f;
#pragma unroll
        for (int j = 0; j < 8; j++) {
            float x1 = acc1[i][j] + bg[j];
            x1 = fmaxf(x1, 0.2f * x1);
            float x2 = acc2[i][j] + bb[j];
            x2 = fmaxf(x2, 0.2f * x2);
            float v = x1 + x2;
            acc1[i][j] = v;
            sq = fmaf(v, v, sq);
        }
#pragma unroll
        for (int m = 8; m >= 1; m >>= 1)
            sq += __shfl_xor_sync(0xffffffffu, sq, m);
        long gr = row0 + r0 + i;
        if (gr < N_NODES) {
            float rn = rsqrtf(fmaxf(sq, 1e-12f));
            float4 o0 = make_float4(acc1[i][0] * rn, acc1[i][1] * rn,
                                    acc1[i][2] * rn, acc1[i][3] * rn);
            float4 o1 = make_float4(acc1[i][4] * rn, acc1[i][5] * rn,
                                    acc1[i][6] * rn, acc1[i][7] * rn);
            reinterpret_cast<float4*>(out + gr * D + c0)[0] = o0;
            reinterpret_cast<float4*>(out + gr * D + c0)[1] = o1;
        }
    }
}

// ------------------------- launch -------------------------
extern "C" void kernel_launch(void* const* d_in, const int* in_sizes, int n_in,
                              void* d_out, int out_size) {
    const int*   erow = (const int*)d_in[0];
    const int*   ecol = (const int*)d_in[1];
    const float* eval = (const float*)d_in[2];
    const float* ego  = (const float*)d_in[3];
    const float* wgc  = (const float*)d_in[4];
    const float* bgc  = (const float*)d_in[5];
    const float* wbi  = (const float*)d_in[6];
    const float* bbi  = (const float*)d_in[7];
    float* out = (float*)d_out;

    // CSR build
    zero_cnt_kernel<<<(N_NODES + 255) / 256, 256>>>();
    hist_kernel<<<(N_EDGES + 255) / 256, 256>>>(erow);
    scan1_kernel<<<SCAN_BLOCKS, 256>>>();
    scan2_kernel<<<1, 256>>>();
    scan3_kernel<<<(N_NODES + 255) / 256, 256>>>();
    fill_kernel<<<(N_EDGES + 255) / 256, 256>>>(erow, ecol, eval);

    // SpMM: warp per row
    long spmm_threads = (long)N_NODES * 32;
    spmm_csr_kernel<<<(int)((spmm_threads + 255) / 256), 256>>>(ego);

    // fused dense transform + leaky_relu + l2 normalize
    cudaFuncSetAttribute(dense_kernel, cudaFuncAttributeMaxDynamicSharedMemorySize, SMEM_BYTES);
    dense_kernel<<<(N_NODES + ROWS_PER_BLK - 1) / ROWS_PER_BLK, 256, SMEM_BYTES>>>(
        ego, wgc, bgc, wbi, bbi, out);
}